// round 6
// baseline (speedup 1.0000x reference)
#include <cuda_runtime.h>
#include <math.h>

// Shape fixed by reference: B=2, L=2048, H=16, E=64
#define B_  2
#define L_  2048
#define H_  16
#define E_  64
#define BH_ 32            // B*H chains
#define CH_ 128           // chunk length along s
#define NC_ 16            // chunks per chain
#define HE_ 1024          // H*E row stride in floats
#define NBLK (BH_ * NC_)  // 512 blocks
#define NT_  256          // threads per block
#define NSUB 4            // sub-groups of 64 channels
#define RPS  32           // rows per sub

// Scratch (__device__ globals; no allocations allowed)
__device__ float g_agg [NBLK * E_];  // per-chunk sum of e*V
__device__ float g_aggE[NBLK];       // per-chunk sum of e
__device__ int   g_flag[NBLK];       // publish flags

__global__ void reset_flags() { g_flag[threadIdx.x] = 0; }

__global__ __launch_bounds__(NT_, 4) void fused_scan_attn(
    const float* __restrict__ keys,
    const float* __restrict__ values,
    const float* __restrict__ w_score,
    float* __restrict__ out)
{
    __shared__ float sV[CH_ * E_];     // 32 KB V tile
    __shared__ float se[CH_];          // e-scores for this chunk
    __shared__ float spEV[NSUB * E_];  // per-sub partial sums of e*V
    __shared__ float spE[NSUB];
    __shared__ float sqEV[NSUB * E_];  // cross-block partial prefix (per sub)
    __shared__ float sqE[NSUB];

    const int tid = threadIdx.x;
    const int blk = blockIdx.x;
    const int bh  = blk >> 4;          // / NC_
    const int c   = blk & 15;          // % NC_
    const int b   = bh >> 4;           // / H_
    const int h   = bh & 15;           // % H_
    const int base = ((b * L_ + c * CH_) * H_ + h) * E_;

    const int d   = tid & 63;          // channel
    const int sub = tid >> 6;          // sub-group 0..3
    const int r0  = sub * RPS;

    // ---- deep load front: 8 independent V float4 loads + 2 K float4 loads
    float4 vr[8];
    {
        const float4* vg = reinterpret_cast<const float4*>(values + base);
        #pragma unroll
        for (int i = 0; i < 8; i++) {
            const int idx = tid + i * NT_;       // float4 index 0..2047
            vr[i] = vg[(idx >> 4) * (HE_ / 4) + (idx & 15)];
        }
    }

    // ---- phase 1: e[row] = exp(0.125 * dot(K[row], w_k)); 2 threads per row
    {
        const int row = tid >> 1, q = tid & 1;   // q selects 32-float half
        const float4* kq = reinterpret_cast<const float4*>(
            keys + base + row * HE_ + q * 32);
        const float4* wq = reinterpret_cast<const float4*>(
            w_score + E_ + q * 32);
        float dot = 0.f;
        #pragma unroll
        for (int j = 0; j < 8; j++) {
            const float4 k4 = kq[j];
            const float4 w4 = wq[j];
            dot += k4.x * w4.x + k4.y * w4.y + k4.z * w4.z + k4.w * w4.w;
        }
        dot += __shfl_xor_sync(0xffffffffu, dot, 1);
        if (q == 0) se[row] = __expf(dot * 0.125f);
    }

    // ---- drain prefetched V tile to smem
    {
        float4* sv4 = reinterpret_cast<float4*>(sV);
        #pragma unroll
        for (int i = 0; i < 8; i++) sv4[tid + i * NT_] = vr[i];
    }
    __syncthreads();

    // ---- phase 3: per-sub partial aggregates over 32 rows
    {
        float sumE = 0.f, sumEV = 0.f;
        #pragma unroll
        for (int r = 0; r < RPS; r++) {
            const float e = se[r0 + r];
            sumE += e;
            sumEV = fmaf(e, sV[(r0 + r) * E_ + d], sumEV);
        }
        spEV[sub * E_ + d] = sumEV;
        if (d == 0) spE[sub] = sumE;
    }
    __syncthreads();

    // combine sub partials -> block aggregate, publish
    if (tid < E_) {
        g_agg[blk * E_ + tid] =
            spEV[tid] + spEV[E_ + tid] + spEV[2 * E_ + tid] + spEV[3 * E_ + tid];
        if (tid == 0)
            g_aggE[blk] = spE[0] + spE[1] + spE[2] + spE[3];
        __threadfence();                 // order agg stores before flag
    }
    __syncthreads();
    if (tid == 0) atomicExch(&g_flag[blk], 1);

    // ---- lookback: wait for ALL predecessors (<=15), plain volatile loads
    if (tid < c) {
        const volatile int* f = (const volatile int*)&g_flag[bh * NC_ + tid];
        while (*f == 0) { }
        __threadfence();                 // acquire predecessors' agg stores
    }
    __syncthreads();

    // ---- phase 4a: cross-block exclusive prefix, split across subs
    {
        float pEV = 0.f;
        for (int t = sub; t < c; t += NSUB)
            pEV += g_agg[(bh * NC_ + t) * E_ + d];
        sqEV[sub * E_ + d] = pEV;
        if (d == 0) {
            float pE = 0.f;
            for (int t = sub; t < c; t += NSUB)
                pE += g_aggE[bh * NC_ + t];
            sqE[sub] = pE;
        }
    }
    __syncthreads();

    // ---- phase 4b: exclusive start + in-sub inclusive scan + output
    {
        float accEV = sqEV[d] + sqEV[E_ + d] + sqEV[2 * E_ + d] + sqEV[3 * E_ + d];
        float accE  = sqE[0] + sqE[1] + sqE[2] + sqE[3];
        #pragma unroll
        for (int s = 0; s < NSUB - 1; s++) {
            if (s < sub) {
                accEV += spEV[s * E_ + d];
                accE  += spE[s];
            }
        }
        float* o = out + base + r0 * HE_ + d;
        #pragma unroll 8
        for (int r = 0; r < RPS; r++) {
            const float e = se[r0 + r];
            accE += e;
            accEV = fmaf(e, sV[(r0 + r) * E_ + d], accEV);
            o[r * HE_] = __fdividef(accEV, accE);
        }
    }
}

extern "C" void kernel_launch(void* const* d_in, const int* in_sizes, int n_in,
                              void* d_out, int out_size) {
    // inputs: 0=queries (unused: a_q cancels in softmax), 1=keys, 2=values,
    //         3=w_score, 4=b_score (unused: cancels)
    const float* keys   = (const float*)d_in[1];
    const float* values = (const float*)d_in[2];
    const float* w      = (const float*)d_in[3];
    float* out = (float*)d_out;

    reset_flags<<<1, NBLK>>>();
    fused_scan_attn<<<NBLK, NT_>>>(keys, values, w, out);
}

// round 7
// speedup vs baseline: 1.1236x; 1.1236x over previous
#include <cuda_runtime.h>
#include <math.h>

// Shape fixed by reference: B=2, L=2048, H=16, E=64
#define B_  2
#define L_  2048
#define H_  16
#define E_  64
#define BH_ 32            // B*H chains
#define CH_ 64            // chunk length along s
#define NC_ 32            // chunks per chain
#define HE_ 1024          // H*E row stride in floats
#define NBLK (BH_ * NC_)  // 1024 blocks
#define NSUB 4            // sub-groups of 64 channels
#define RPS  16           // rows per sub

// Scratch (__device__ globals; no allocations allowed)
__device__ float g_E   [BH_ * L_];    // e-scores (1 MB)
__device__ float g_agg [NBLK * E_];   // per-chunk sum of e*V
__device__ float g_aggE[NBLK];        // per-chunk sum of e

// ---------------- K1: e-scores + per-chunk aggregates (streaming) ----------
__global__ __launch_bounds__(256, 8) void k_aggregate(
    const float* __restrict__ keys,
    const float* __restrict__ values,
    const float* __restrict__ w_score)
{
    __shared__ float sV[CH_ * E_];     // 16 KB V tile
    __shared__ float se[CH_];
    __shared__ float spEV[NSUB * E_];
    __shared__ float spE[NSUB];

    const int tid = threadIdx.x;
    const int blk = blockIdx.x;
    const int bh  = blk >> 5;          // / NC_
    const int c   = blk & 31;          // % NC_
    const int b   = bh >> 4;
    const int h   = bh & 15;
    const int base = ((b * L_ + c * CH_) * H_ + h) * E_;

    const int d   = tid & 63;
    const int sub = tid >> 6;
    const int r0  = sub * RPS;

    // e[row] = exp(0.125 * dot(K[row], w_k)); 4 threads per row
    {
        const int row = tid >> 2, q = tid & 3;
        const float4* kq = reinterpret_cast<const float4*>(
            keys + base + row * HE_ + q * 16);
        const float4* wq = reinterpret_cast<const float4*>(
            w_score + E_ + q * 16);
        float dot = 0.f;
        #pragma unroll
        for (int j = 0; j < 4; j++) {
            const float4 k4 = kq[j];
            const float4 w4 = wq[j];
            dot += k4.x * w4.x + k4.y * w4.y + k4.z * w4.z + k4.w * w4.w;
        }
        dot += __shfl_xor_sync(0xffffffffu, dot, 1);
        dot += __shfl_xor_sync(0xffffffffu, dot, 2);
        if (q == 0) {
            const float e = __expf(dot * 0.125f);
            se[row] = e;
            g_E[bh * L_ + c * CH_ + row] = e;
        }
    }

    // stage V tile (float4, coalesced)
    {
        const float4* vg = reinterpret_cast<const float4*>(values + base);
        float4* sv4 = reinterpret_cast<float4*>(sV);
        #pragma unroll
        for (int i = 0; i < 4; i++) {
            const int idx = tid + i * 256;
            sv4[idx] = vg[(idx >> 4) * (HE_ / 4) + (idx & 15)];
        }
    }
    __syncthreads();

    // per-sub partial aggregates over 16 rows (all 256 threads)
    {
        float sumE = 0.f, sumEV = 0.f;
        #pragma unroll
        for (int r = 0; r < RPS; r++) {
            const float e = se[r0 + r];
            sumE += e;
            sumEV = fmaf(e, sV[(r0 + r) * E_ + d], sumEV);
        }
        spEV[sub * E_ + d] = sumEV;
        if (d == 0) spE[sub] = sumE;
    }
    __syncthreads();

    if (tid < E_) {
        g_agg[blk * E_ + tid] =
            spEV[tid] + spEV[E_ + tid] + spEV[2 * E_ + tid] + spEV[3 * E_ + tid];
        if (tid == 0)
            g_aggE[blk] = spE[0] + spE[1] + spE[2] + spE[3];
    }
}

// ---------------- K2: prefix from aggregates + output scan ------------------
__global__ __launch_bounds__(256, 8) void k_output(
    const float* __restrict__ values,
    float* __restrict__ out)
{
    __shared__ float sV[CH_ * E_];
    __shared__ float se[CH_];
    __shared__ float spEV[NSUB * E_];
    __shared__ float spE[NSUB];
    __shared__ float sqEV[NSUB * E_];
    __shared__ float sqE[NSUB];

    const int tid = threadIdx.x;
    const int blk = blockIdx.x;
    const int bh  = blk >> 5;
    const int c   = blk & 31;
    const int b   = bh >> 4;
    const int h   = bh & 15;
    const int base = ((b * L_ + c * CH_) * H_ + h) * E_;

    const int d   = tid & 63;
    const int sub = tid >> 6;
    const int r0  = sub * RPS;

    // load e chunk (64 floats) — L2 hit
    if (tid < CH_) se[tid] = g_E[bh * L_ + c * CH_ + tid];

    // stage V tile — L2 hit (read by K1 just before)
    {
        const float4* vg = reinterpret_cast<const float4*>(values + base);
        float4* sv4 = reinterpret_cast<float4*>(sV);
        #pragma unroll
        for (int i = 0; i < 4; i++) {
            const int idx = tid + i * 256;
            sv4[idx] = vg[(idx >> 4) * (HE_ / 4) + (idx & 15)];
        }
    }

    // cross-block exclusive prefix from aggregates (visible: kernel boundary)
    {
        float pEV = 0.f;
        for (int t = sub; t < c; t += NSUB)
            pEV += g_agg[(bh * NC_ + t) * E_ + d];
        sqEV[sub * E_ + d] = pEV;
        if (d == 0) {
            float pE = 0.f;
            for (int t = sub; t < c; t += NSUB)
                pE += g_aggE[bh * NC_ + t];
            sqE[sub] = pE;
        }
    }
    __syncthreads();

    // recompute per-sub partials of THIS chunk (for lower-sub offsets)
    {
        float sumE = 0.f, sumEV = 0.f;
        #pragma unroll
        for (int r = 0; r < RPS; r++) {
            const float e = se[r0 + r];
            sumE += e;
            sumEV = fmaf(e, sV[(r0 + r) * E_ + d], sumEV);
        }
        spEV[sub * E_ + d] = sumEV;
        if (d == 0) spE[sub] = sumE;
    }
    __syncthreads();

    // exclusive start + in-sub inclusive scan + output
    {
        float accEV = sqEV[d] + sqEV[E_ + d] + sqEV[2 * E_ + d] + sqEV[3 * E_ + d];
        float accE  = sqE[0] + sqE[1] + sqE[2] + sqE[3];
        #pragma unroll
        for (int s = 0; s < NSUB - 1; s++) {
            if (s < sub) {
                accEV += spEV[s * E_ + d];
                accE  += spE[s];
            }
        }
        float* o = out + base + r0 * HE_ + d;
        #pragma unroll
        for (int r = 0; r < RPS; r++) {
            const float e = se[r0 + r];
            accE += e;
            accEV = fmaf(e, sV[(r0 + r) * E_ + d], accEV);
            o[r * HE_] = __fdividef(accEV, accE);
        }
    }
}

extern "C" void kernel_launch(void* const* d_in, const int* in_sizes, int n_in,
                              void* d_out, int out_size) {
    // inputs: 0=queries (unused: a_q cancels in softmax), 1=keys, 2=values,
    //         3=w_score, 4=b_score (unused: cancels)
    const float* keys   = (const float*)d_in[1];
    const float* values = (const float*)d_in[2];
    const float* w      = (const float*)d_in[3];
    float* out = (float*)d_out;

    k_aggregate<<<NBLK, 256>>>(keys, values, w);
    k_output<<<NBLK, 256>>>(values, out);
}

// round 8
// speedup vs baseline: 1.2765x; 1.1361x over previous
#include <cuda_runtime.h>
#include <math.h>

// Shape fixed by reference: B=2, L=2048, H=16, E=64
#define B_  2
#define L_  2048
#define H_  16
#define E_  64
#define BH_ 32            // B*H chains
#define CH_ 64            // chunk length along s
#define NC_ 32            // chunks per chain
#define HE_ 1024          // H*E row stride in floats
#define NBLK (BH_ * NC_)  // 1024 blocks
#define NSUB 4            // sub-groups of 64 channels
#define RPS  16           // rows per sub

// Scratch (__device__ globals; no allocations allowed)
__device__ float g_E   [BH_ * L_];           // e-scores
__device__ float g_agg [NBLK * E_];          // per-chunk sum of e*V
__device__ float g_aggE[NBLK];               // per-chunk sum of e
__device__ float g_sub [NBLK * NSUB * E_];   // per-sub partial sums of e*V

// ---------------- K1: e-scores + per-chunk/per-sub aggregates --------------
__global__ __launch_bounds__(256, 8) void k_aggregate(
    const float* __restrict__ keys,
    const float* __restrict__ values,
    const float* __restrict__ w_score)
{
    __shared__ float sV[CH_ * E_];     // 16 KB V tile
    __shared__ float se[CH_];
    __shared__ float spEV[NSUB * E_];
    __shared__ float spE[NSUB];

    const int tid = threadIdx.x;
    const int blk = blockIdx.x;
    const int bh  = blk >> 5;          // / NC_
    const int c   = blk & 31;          // % NC_
    const int b   = bh >> 4;
    const int h   = bh & 15;
    const int base = ((b * L_ + c * CH_) * H_ + h) * E_;

    const int d   = tid & 63;
    const int sub = tid >> 6;
    const int r0  = sub * RPS;

    // e[row] = exp(0.125 * dot(K[row], w_k)); 4 threads per row
    {
        const int row = tid >> 2, q = tid & 3;
        const float4* kq = reinterpret_cast<const float4*>(
            keys + base + row * HE_ + q * 16);
        const float4* wq = reinterpret_cast<const float4*>(
            w_score + E_ + q * 16);
        float dot = 0.f;
        #pragma unroll
        for (int j = 0; j < 4; j++) {
            const float4 k4 = kq[j];
            const float4 w4 = wq[j];
            dot += k4.x * w4.x + k4.y * w4.y + k4.z * w4.z + k4.w * w4.w;
        }
        dot += __shfl_xor_sync(0xffffffffu, dot, 1);
        dot += __shfl_xor_sync(0xffffffffu, dot, 2);
        if (q == 0) {
            const float e = __expf(dot * 0.125f);
            se[row] = e;
            g_E[bh * L_ + c * CH_ + row] = e;
        }
    }

    // stage V tile (float4, coalesced)
    {
        const float4* vg = reinterpret_cast<const float4*>(values + base);
        float4* sv4 = reinterpret_cast<float4*>(sV);
        #pragma unroll
        for (int i = 0; i < 4; i++) {
            const int idx = tid + i * 256;
            sv4[idx] = vg[(idx >> 4) * (HE_ / 4) + (idx & 15)];
        }
    }
    __syncthreads();

    // per-sub partial aggregates over 16 rows; persist per-sub EV partials
    {
        float sumE = 0.f, sumEV = 0.f;
        #pragma unroll
        for (int r = 0; r < RPS; r++) {
            const float e = se[r0 + r];
            sumE += e;
            sumEV = fmaf(e, sV[(r0 + r) * E_ + d], sumEV);
        }
        g_sub[(blk * NSUB + sub) * E_ + d] = sumEV;   // direct store
        spEV[sub * E_ + d] = sumEV;
        if (d == 0) spE[sub] = sumE;
    }
    __syncthreads();

    if (tid < E_) {
        g_agg[blk * E_ + tid] =
            spEV[tid] + spEV[E_ + tid] + spEV[2 * E_ + tid] + spEV[3 * E_ + tid];
        if (tid == 0)
            g_aggE[blk] = spE[0] + spE[1] + spE[2] + spE[3];
    }
}

// ---------------- K2: prefix + output scan (divide-free) --------------------
__global__ __launch_bounds__(256, 8) void k_output(
    const float* __restrict__ values,
    float* __restrict__ out)
{
    __shared__ float se[CH_];          // e-scores for this chunk
    __shared__ float srcp[CH_];        // 1 / cumulative-E per row
    __shared__ float sqEV[NSUB * E_];  // chunk-prefix partials

    const int tid = threadIdx.x;
    const int blk = blockIdx.x;
    const int bh  = blk >> 5;
    const int c   = blk & 31;
    const int b   = bh >> 4;
    const int h   = bh & 15;
    const int base = ((b * L_ + c * CH_) * H_ + h) * E_;

    const int d   = tid & 63;
    const int sub = tid >> 6;
    const int r0  = sub * RPS;

    // ---- everyone: chunk-prefix EV loads, split NSUB ways
    {
        float pEV = 0.f;
        for (int t = sub; t < c; t += NSUB)
            pEV += g_agg[(bh * NC_ + t) * E_ + d];
        sqEV[sub * E_ + d] = pEV;
    }

    // ---- warp 7: E-side. preE reduce + pair-scan + reciprocals (2 MUFU)
    if (tid >= 224) {
        const int lane = tid & 31;
        // preE = sum of predecessor chunk E-aggregates
        float pe = (lane < c) ? g_aggE[bh * NC_ + lane] : 0.f;
        #pragma unroll
        for (int o = 16; o; o >>= 1) pe += __shfl_xor_sync(0xffffffffu, pe, o);
        // load this chunk's 64 e-scores, 2 per lane
        const float2 e2 = reinterpret_cast<const float2*>(
            g_E + bh * L_ + c * CH_)[lane];
        // inclusive pair-scan over the warp
        const float p = e2.x + e2.y;
        float incl = p;
        #pragma unroll
        for (int o = 1; o < 32; o <<= 1) {
            const float t = __shfl_up_sync(0xffffffffu, incl, o);
            if (lane >= o) incl += t;
        }
        const float excl = incl - p;
        se[2 * lane]     = e2.x;
        se[2 * lane + 1] = e2.y;
        srcp[2 * lane]     = __fdividef(1.f, pe + excl + e2.x);
        srcp[2 * lane + 1] = __fdividef(1.f, pe + incl);
    }
    __syncthreads();

    // ---- exclusive EV start for this thread
    float accEV = sqEV[d] + sqEV[E_ + d] + sqEV[2 * E_ + d] + sqEV[3 * E_ + d];
    #pragma unroll
    for (int s = 0; s < NSUB - 1; s++)
        if (s < sub) accEV += g_sub[(blk * NSUB + s) * E_ + d];

    // ---- inclusive scan over 16 rows, V direct from L2, divide-free output
    const float* v = values + base + r0 * HE_ + d;
    float*       o = out    + base + r0 * HE_ + d;
    #pragma unroll
    for (int r = 0; r < RPS; r++) {
        accEV = fmaf(se[r0 + r], v[r * HE_], accEV);
        o[r * HE_] = accEV * srcp[r0 + r];
    }
}

extern "C" void kernel_launch(void* const* d_in, const int* in_sizes, int n_in,
                              void* d_out, int out_size) {
    // inputs: 0=queries (unused: a_q cancels in softmax), 1=keys, 2=values,
    //         3=w_score, 4=b_score (unused: cancels)
    const float* keys   = (const float*)d_in[1];
    const float* values = (const float*)d_in[2];
    const float* w      = (const float*)d_in[3];
    float* out = (float*)d_out;

    k_aggregate<<<NBLK, 256>>>(keys, values, w);
    k_output<<<NBLK, 256>>>(values, out);
}